// round 9
// baseline (speedup 1.0000x reference)
#include <cuda_runtime.h>
#include <math.h>

// Problem sizes (fixed by the dataset)
#define TT 512
#define BB 256
#define II 256
#define HH 256
#define NG 32          // batch groups (8 rows each)

// -------- scratch (device globals: allocation-free contract) --------
__device__ float g_xp[(size_t)3 * TT * BB * HH];     // projections [mat][t][b][h]
// per-slice packed U: g_us[r] = 3 mats x 4096 quads, quad idx (qp*64+j)*8+ks
__device__ float g_us[4][3 * 16384];
// per-step exchange buffers (single-buffered; safety via flag protocol)
__device__ float g_eh[NG][4][512];                   // e*h export [row*64+jj]
__device__ float g_hx[NG][4][512];                   // h_new export
__device__ float g_S [NG][4][8];                     // partial softmax sums
__device__ unsigned int g_fl[NG][4][TT][2];          // [stage]: 0=eh, 1=h

// ---------------- asm helpers ----------------
__device__ __forceinline__ void ffma2(unsigned long long& d, unsigned long long a,
                                      unsigned long long b) {
    asm("fma.rn.f32x2 %0, %1, %2, %0;" : "+l"(d) : "l"(a), "l"(b));
}
__device__ __forceinline__ unsigned long long fdup(float v) {
    unsigned long long r; unsigned int u = __float_as_uint(v);
    asm("mov.b64 %0, {%1, %1};" : "=l"(r) : "r"(u));
    return r;
}
__device__ __forceinline__ float ffold(unsigned long long v) {
    return __uint_as_float((unsigned int)(v & 0xffffffffull)) +
           __uint_as_float((unsigned int)(v >> 32));
}
__device__ __forceinline__ void st_release_u32(unsigned int* p, unsigned int v) {
    asm volatile("st.release.gpu.global.u32 [%0], %1;" :: "l"(p), "r"(v) : "memory");
}
__device__ __forceinline__ unsigned int ld_acquire_u32(const unsigned int* p) {
    unsigned int v;
    asm volatile("ld.acquire.gpu.global.u32 %0, [%1];" : "=r"(v) : "l"(p) : "memory");
    return v;
}
__device__ __forceinline__ void wait_flag(const unsigned int* p) {
    while (ld_acquire_u32(p) == 0u) { }
}
__device__ __forceinline__ float tanh_fast(float x) {
    float r; asm("tanh.approx.f32 %0, %1;" : "=f"(r) : "f"(x)); return r;
}

// ---------------------------------------------------------------
// Kernel 0: zero the flags (runs first on every graph replay)
// ---------------------------------------------------------------
__global__ void zero_flags() {
    int i = blockIdx.x * blockDim.x + threadIdx.x;
    if (i < NG * 4 * TT * 2) ((unsigned int*)g_fl)[i] = 0u;
}

// ---------------------------------------------------------------
// Kernel 1: pack U into per-slice smem-ready layout.
// g_us[r][m*16384 + ((qp*64+j)*8+ks)*4 + e] = U_m[(64r+j)*256 + (qp*8+ks)*4+e]
// ---------------------------------------------------------------
__global__ void reblock_U(const float* __restrict__ Uz,
                          const float* __restrict__ Ua,
                          const float* __restrict__ Uh) {
    int idx = blockIdx.x * blockDim.x + threadIdx.x;
    if (idx >= 3 * HH * HH) return;
    int m  = idx >> 16;
    int rem = idx & 65535;
    int jg = rem >> 8;
    int k  = rem & 255;
    int r  = jg >> 6, j = jg & 63;
    int kq = k >> 2, e = k & 3;
    int qp = kq >> 3, ks = kq & 7;
    const float* U = (m == 0) ? Uz : ((m == 1) ? Ua : Uh);
    g_us[r][m * 16384 + (((qp * 64 + j) * 8 + ks) << 2) + e] = U[jg * 256 + k];
}

// ---------------------------------------------------------------
// Kernel 2: projection GEMM with FFMA2 (unchanged from R8)
// ---------------------------------------------------------------
__global__ __launch_bounds__(256) void proj_gemm(
    const float* __restrict__ x,
    const float* __restrict__ Wz,
    const float* __restrict__ Wa,
    const float* __restrict__ Wh) {
    constexpr int BM = 128, BN = 128, BK = 16;
    __shared__ float As[BK][BM];
    __shared__ float Bs[BK][BN];

    const int m0 = blockIdx.x * BM;
    const int n0 = blockIdx.y * BN;
    const int mat = n0 >> 8;
    const int jb  = n0 & 255;
    const float* W = (mat == 0) ? Wz : ((mat == 1) ? Wa : Wh);

    const int tid = threadIdx.x;
    const int tx = tid & 15;
    const int ty = tid >> 4;
    const int lr = tid >> 2;
    const int lc = (tid & 3) * 4;

    unsigned long long acc2[8][4];
#pragma unroll
    for (int i = 0; i < 8; ++i)
#pragma unroll
        for (int p = 0; p < 4; ++p) acc2[i][p] = 0ull;

    for (int k0 = 0; k0 < II; k0 += BK) {
        float4 a0 = *(const float4*)(x + (size_t)(m0 + lr)      * II + k0 + lc);
        float4 a1 = *(const float4*)(x + (size_t)(m0 + lr + 64) * II + k0 + lc);
        float4 b0 = *(const float4*)(W + (size_t)(jb + lr)      * II + k0 + lc);
        float4 b1 = *(const float4*)(W + (size_t)(jb + lr + 64) * II + k0 + lc);

        __syncthreads();
        As[lc + 0][lr] = a0.x; As[lc + 1][lr] = a0.y; As[lc + 2][lr] = a0.z; As[lc + 3][lr] = a0.w;
        As[lc + 0][lr + 64] = a1.x; As[lc + 1][lr + 64] = a1.y; As[lc + 2][lr + 64] = a1.z; As[lc + 3][lr + 64] = a1.w;
        Bs[lc + 0][lr] = b0.x; Bs[lc + 1][lr] = b0.y; Bs[lc + 2][lr] = b0.z; Bs[lc + 3][lr] = b0.w;
        Bs[lc + 0][lr + 64] = b1.x; Bs[lc + 1][lr + 64] = b1.y; Bs[lc + 2][lr + 64] = b1.z; Bs[lc + 3][lr + 64] = b1.w;
        __syncthreads();

#pragma unroll
        for (int kk = 0; kk < BK; ++kk) {
            float4 ra0 = *(const float4*)&As[kk][ty * 8];
            float4 ra1 = *(const float4*)&As[kk][ty * 8 + 4];
            ulonglong2 rb0 = *(const ulonglong2*)&Bs[kk][tx * 8];
            ulonglong2 rb1 = *(const ulonglong2*)&Bs[kk][tx * 8 + 4];
            unsigned long long pa[8];
            pa[0] = fdup(ra0.x); pa[1] = fdup(ra0.y); pa[2] = fdup(ra0.z); pa[3] = fdup(ra0.w);
            pa[4] = fdup(ra1.x); pa[5] = fdup(ra1.y); pa[6] = fdup(ra1.z); pa[7] = fdup(ra1.w);
#pragma unroll
            for (int i = 0; i < 8; ++i) {
                ffma2(acc2[i][0], pa[i], rb0.x);
                ffma2(acc2[i][1], pa[i], rb0.y);
                ffma2(acc2[i][2], pa[i], rb1.x);
                ffma2(acc2[i][3], pa[i], rb1.y);
            }
        }
    }

#pragma unroll
    for (int i = 0; i < 8; ++i) {
        int row = m0 + ty * 8 + i;
        int b = row >> 9;             // T = 512
        int t = row & (TT - 1);
        float* o = g_xp + ((size_t)mat * TT + t) * (size_t)(BB * HH)
                        + (size_t)b * HH + jb + tx * 8;
        *(float4*)(o)     = *(const float4*)&acc2[i][0];
        *(float4*)(o + 4) = *(const float4*)&acc2[i][2];
    }
}

// ---------------------------------------------------------------
// Kernel 3: j-sliced recurrent scan.
// 128 CTAs = 32 groups x 4 column-slices, 512 threads each.
// CTA (g, r) owns columns jg in [64r, 64r+64) with FULL k in smem (192KB).
// Per step: only e*h (2KB) and h_new (2KB) cross CTAs.
// GEMV threading: lane = (j&3)*8 + kseg; reduce over kseg via shfl_xor.
// Thread (j, kseg) finalizes (row = kseg, column jg).
// ---------------------------------------------------------------
__global__ __launch_bounds__(512, 1) void scan_kernel(
    const float* __restrict__ bz,
    const float* __restrict__ va,
    const float* __restrict__ bh,
    float* __restrict__ out) {
    extern __shared__ float sm[];
    float* sU    = sm;               // 49152 floats (192KB)
    float* hf    = sm + 49152;       // h_full  [8 rows][256 k]  (2048)
    float* ef    = sm + 51200;       // eh_full [8 rows][256 k]  (2048)
    float* sx    = sm + 53248;       // x stage [3][8][68]       (1632)
    float* sredA = sm + 54880;       // S warp partials [16][8]  (128)
    float* sS    = sm + 55008;       // final softmax sums [8]

    const int tid = threadIdx.x;
    const int g = blockIdx.x >> 2;
    const int r = blockIdx.x & 3;
    const int b0 = g * 8;

    // ---- load own U slice (contiguous 192KB) ----
    {
        const float4* src = (const float4*)g_us[r];
        float4* dst = (float4*)sU;
        for (int i = tid; i < 12288; i += 512) dst[i] = src[i];
    }
    ((float4*)hf)[tid] = make_float4(0.f, 0.f, 0.f, 0.f);   // 512*16B = 8KB
    __syncthreads();

    const int lane = tid & 31;
    const int w    = tid >> 5;
    const int jA   = w * 4 + ((lane >> 3) & 3);   // 0..63
    const int ksg  = lane & 7;                    // k-segment AND finalize row
    const int jg   = r * 64 + jA;

    const float bzv = bz[jg], vav = va[jg], bhv = bh[jg];
    float h = 0.f;                                 // state (row=ksg, col=jg)

    // export/remap identity
    const int rowX = tid >> 6;                     // 0..7
    const int jjX  = tid & 63;

    const ulonglong2* U2 = (const ulonglong2*)sU;
    const ulonglong2* H2 = (const ulonglong2*)hf;
    const ulonglong2* E2 = (const ulonglong2*)ef;

    unsigned int* myfl = &g_fl[g][r][0][0];

    for (int t = 0; t < TT; ++t) {
        // ---- phase 0: x stage + h import ----
        if (tid < 384) {
            int m  = tid >> 7;
            int off = tid & 127;
            int row = off >> 4, q4 = off & 15;
            const float4* xs = (const float4*)(g_xp
                + ((size_t)(m * TT + t) * BB + (b0 + row)) * HH + r * 64 + q4 * 4);
            *(float4*)(sx + m * 544 + row * 68 + q4 * 4) = *xs;
            if (t > 0) {
                int slot = tid >> 7;               // 0..2
                int c = slot + (slot >= r ? 1 : 0);
                wait_flag(&g_fl[g][c][t - 1][1]);
                float4 v = ((const float4*)g_hx[g][c])[off];
                ((float4*)hf)[row * 64 + c * 16 + q4] = v;
            }
        }
        __syncthreads();

        // ---- stage A: full-k GEMV for own columns (z and attention) ----
        unsigned long long za[8], aa[8];
#pragma unroll
        for (int q = 0; q < 8; ++q) { za[q] = 0ull; aa[q] = 0ull; }
#pragma unroll
        for (int qp = 0; qp < 8; ++qp) {
            const int uq = (qp * 64 + jA) * 8 + ksg;
            ulonglong2 uz = U2[uq];
            ulonglong2 ua = U2[4096 + uq];
            const int kq = qp * 8 + ksg;
#pragma unroll
            for (int rr = 0; rr < 8; ++rr) {
                ulonglong2 hk = H2[rr * 64 + kq];
                ffma2(za[rr], hk.x, uz.x); ffma2(za[rr], hk.y, uz.y);
                ffma2(aa[rr], hk.x, ua.x); ffma2(aa[rr], hk.y, ua.y);
            }
        }
        float zf[8], af[8];
#pragma unroll
        for (int rr = 0; rr < 8; ++rr) { zf[rr] = ffold(za[rr]); af[rr] = ffold(aa[rr]); }
#pragma unroll
        for (int d = 1; d < 8; d <<= 1) {
#pragma unroll
            for (int rr = 0; rr < 8; ++rr) {
                zf[rr] += __shfl_xor_sync(0xffffffffu, zf[rr], d);
                af[rr] += __shfl_xor_sync(0xffffffffu, af[rr], d);
            }
        }
        float zas = 0.f, aas = 0.f;
#pragma unroll
        for (int rr = 0; rr < 8; ++rr) if (ksg == rr) { zas = zf[rr]; aas = af[rr]; }

        const float xzv = sx[ksg * 68 + jA];
        const float xav = sx[544 + ksg * 68 + jA];
        const float z = 1.f / (1.f + __expf(-(xzv + zas + bzv)));
        const float e = __expf(tanh_fast(xav + aas) * vav);
        ef[ksg * 256 + jg] = e * h;

        // warp-level partial softmax sum (over 4 j in this warp, row=ksg)
        float se = e;
        se += __shfl_xor_sync(0xffffffffu, se, 8);
        se += __shfl_xor_sync(0xffffffffu, se, 16);
        if ((lane >> 3) == 0) sredA[w * 8 + ksg] = se;
        __syncthreads();

        // ---- export eh + partial S ----
        {
            float v = ef[rowX * 256 + r * 64 + jjX];
            g_eh[g][r][rowX * 64 + jjX] = v;
        }
        if (tid < 8) {
            float s = 0.f;
#pragma unroll
            for (int w2 = 0; w2 < 16; ++w2) s += sredA[w2 * 8 + tid];
            g_S[g][r][tid] = s;
        }
        __syncthreads();
        if (tid == 0) st_release_u32(&myfl[2 * t], 1u);

        // ---- import eh + finalize S ----
        if (tid < 384) {
            int slot = tid >> 7;
            int c = slot + (slot >= r ? 1 : 0);
            int off = tid & 127;
            wait_flag(&g_fl[g][c][t][0]);
            float4 v = ((const float4*)g_eh[g][c])[off];
            int row = off >> 4, q4 = off & 15;
            ((float4*)ef)[row * 64 + c * 16 + q4] = v;
        } else if (tid < 392) {
            int row = tid - 384;
#pragma unroll
            for (int c = 0; c < 4; ++c) if (c != r) wait_flag(&g_fl[g][c][t][0]);
            float s = 0.f;
#pragma unroll
            for (int c = 0; c < 4; ++c) s += g_S[g][c][row];
            sS[row] = s;
        }
        __syncthreads();

        // ---- stage B: full-k GEMV of e*h (candidate) ----
        unsigned long long dd[8];
#pragma unroll
        for (int q = 0; q < 8; ++q) dd[q] = 0ull;
#pragma unroll
        for (int qp = 0; qp < 8; ++qp) {
            ulonglong2 uh = U2[8192 + (qp * 64 + jA) * 8 + ksg];
            const int kq = qp * 8 + ksg;
#pragma unroll
            for (int rr = 0; rr < 8; ++rr) {
                ulonglong2 ek = E2[rr * 64 + kq];
                ffma2(dd[rr], ek.x, uh.x); ffma2(dd[rr], ek.y, uh.y);
            }
        }
        float df[8];
#pragma unroll
        for (int rr = 0; rr < 8; ++rr) df[rr] = ffold(dd[rr]);
#pragma unroll
        for (int d = 1; d < 8; d <<= 1) {
#pragma unroll
            for (int rr = 0; rr < 8; ++rr)
                df[rr] += __shfl_xor_sync(0xffffffffu, df[rr], d);
        }
        float ds = 0.f;
#pragma unroll
        for (int rr = 0; rr < 8; ++rr) if (ksg == rr) ds = df[rr];

        const float xhv = sx[1088 + ksg * 68 + jA];
        const float ht = tanhf(xhv + ds / sS[ksg] + bhv);
        const float hn = h + z * (ht - h);
        h = hn;
        hf[ksg * 256 + jg] = hn;
        __syncthreads();

        // ---- export h_new + write outputs (coalesced via smem) ----
        {
            float v = hf[rowX * 256 + r * 64 + jjX];
            out[((size_t)(b0 + rowX) * TT + t) * HH + r * 64 + jjX] = v;
            g_hx[g][r][rowX * 64 + jjX] = v;
        }
        __syncthreads();
        if (tid == 0) st_release_u32(&myfl[2 * t + 1], 1u);
    }

    // h_last appended after outputs [B,T,H]
    float* hl = out + (size_t)BB * TT * HH;
    hl[(size_t)(b0 + rowX) * HH + r * 64 + jjX] = hf[rowX * 256 + r * 64 + jjX];
}

// ---------------------------------------------------------------
// kernel_launch: zero flags -> pack U -> GEMM -> scan
// Inputs: x, W_z, U_z, b_z, W_a, U_a, v_a, W_h, U_h, b_h
// ---------------------------------------------------------------
extern "C" void kernel_launch(void* const* d_in, const int* in_sizes, int n_in,
                              void* d_out, int out_size) {
    const float* x  = (const float*)d_in[0];
    const float* Wz = (const float*)d_in[1];
    const float* Uz = (const float*)d_in[2];
    const float* bz = (const float*)d_in[3];
    const float* Wa = (const float*)d_in[4];
    const float* Ua = (const float*)d_in[5];
    const float* va = (const float*)d_in[6];
    const float* Wh = (const float*)d_in[7];
    const float* Uh = (const float*)d_in[8];
    const float* bh = (const float*)d_in[9];
    float* out = (float*)d_out;

    static bool attr_set = false;
    if (!attr_set) {
        cudaFuncSetAttribute(scan_kernel, cudaFuncAttributeMaxDynamicSharedMemorySize,
                             55016 * 4);
        attr_set = true;
    }

    zero_flags<<<(NG * 4 * TT * 2 + 255) / 256, 256>>>();
    reblock_U<<<(3 * HH * HH + 255) / 256, 256>>>(Uz, Ua, Uh);

    dim3 grid_g((BB * TT) / 128, (3 * HH) / 128);
    proj_gemm<<<grid_g, 256>>>(x, Wz, Wa, Wh);

    scan_kernel<<<NG * 4, 512, 55016 * 4>>>(bz, va, bh, out);
}